// round 11
// baseline (speedup 1.0000x reference)
#include <cuda_runtime.h>
#include <cuda_fp16.h>
#include <cstdint>

#define Bsz 4
#define Sq  2048
#define Emb 768
#define NH  12
#define HD  64
#define NT  (Sq / 64)            // 32 k-tiles of 64 keys
#define L2E 1.4426950408889634f

// Q, K: [B,H,S,D] half, D pair-interleaved within 16-groups.
// V: [B,H,D,S] half, S pair-interleaved within 16-groups.
// Q pre-scaled by 0.125 * log2(e).
__device__ __half g_Q[(size_t)Bsz * NH * Sq * HD];
__device__ __half g_K[(size_t)Bsz * NH * Sq * HD];
__device__ __half g_V[(size_t)Bsz * NH * Sq * HD];

// ---------------------------------------------------------------------------
// helpers
// ---------------------------------------------------------------------------
__device__ __forceinline__ unsigned h2pk(float lo, float hi) {
    unsigned r;
    asm("cvt.rn.f16x2.f32 %0, %1, %2;" : "=r"(r) : "f"(hi), "f"(lo));
    return r;
}
__device__ __forceinline__ float ex2f(float x) {
    float r;
    asm("ex2.approx.f32 %0, %1;" : "=f"(r) : "f"(x));
    return r;
}
__device__ __forceinline__ void mma_f16(float* d, const unsigned* a, const unsigned* b) {
    asm volatile(
        "mma.sync.aligned.m16n8k16.row.col.f32.f16.f16.f32 "
        "{%0,%1,%2,%3}, {%4,%5,%6,%7}, {%8,%9}, {%0,%1,%2,%3};"
        : "+f"(d[0]), "+f"(d[1]), "+f"(d[2]), "+f"(d[3])
        : "r"(a[0]), "r"(a[1]), "r"(a[2]), "r"(a[3]), "r"(b[0]), "r"(b[1]));
}
__device__ __forceinline__ void cpa16(void* s, const void* g) {
    unsigned sa = (unsigned)__cvta_generic_to_shared(s);
    asm volatile("cp.async.cg.shared.global [%0], [%1], 16;" :: "r"(sa), "l"(g));
}
#define CP_COMMIT()  asm volatile("cp.async.commit_group;")
#define CP_WAIT(N)   asm volatile("cp.async.wait_group %0;" :: "n"(N))

// ---------------------------------------------------------------------------
// Kernel 1: fused QKV projection, fp16 mma (fp32 accum), reg-pipelined loads.
// Row stride 36 words (== 4 mod 32) -> conflict-free fragment LDS.
// ---------------------------------------------------------------------------
#define XW 36

__global__ __launch_bounds__(256, 2)
void qkv_kernel(const float* __restrict__ X,
                const float* __restrict__ Wq, const float* __restrict__ bq,
                const float* __restrict__ Wk, const float* __restrict__ bk,
                const float* __restrict__ Wv, const float* __restrict__ bv)
{
    __shared__ uint32_t Xs[128][XW];
    __shared__ uint32_t Ws[128][XW];

    const int tid = threadIdx.x;
    const int w   = tid >> 5;
    const int l   = tid & 31;
    const int wm  = w >> 1;
    const int wn  = w & 1;
    const int lg  = l >> 2;
    const int lt  = l & 3;

    const int bx    = blockIdx.x;
    const int row0  = blockIdx.y * 128;
    const int which = bx / 6;
    const int o0    = (bx % 6) * 128;

    const float* W    = (which == 0) ? Wq : (which == 1) ? Wk : Wv;
    const float* bias = (which == 0) ? bq : (which == 1) ? bk : bv;
    __half*      dst  = (which == 0) ? g_Q : (which == 1) ? g_K : g_V;
    const float scale = (which == 0) ? (0.125f * L2E) : 1.0f;

    float acc[2][8][4];
    #pragma unroll
    for (int mt = 0; mt < 2; mt++)
        #pragma unroll
        for (int nt = 0; nt < 8; nt++)
            #pragma unroll
            for (int j = 0; j < 4; j++) acc[mt][nt][j] = 0.f;

    const int cr = tid >> 1;           // row 0..127
    const int cg = tid & 1;            // k16-group within k-tile

    const float* Xp = &X[(size_t)(row0 + cr) * Emb + cg * 16];
    const float* Wp = &W[(size_t)(o0 + cr) * Emb + cg * 16];

    // preload kt = 0
    float4 px[4], pw[4];
    #pragma unroll
    for (int u = 0; u < 4; u++) {
        px[u] = *(const float4*)(Xp + 4 * u);
        pw[u] = *(const float4*)(Wp + 4 * u);
    }

    for (int kt = 0; kt < Emb / 32; kt++) {
        // store prefetched tile (cvt fp16, pair-interleave)
        {
            uint4 s1 = make_uint4(h2pk(px[0].x,px[0].y), h2pk(px[2].x,px[2].y),
                                  h2pk(px[0].z,px[0].w), h2pk(px[2].z,px[2].w));
            uint4 s2 = make_uint4(h2pk(px[1].x,px[1].y), h2pk(px[3].x,px[3].y),
                                  h2pk(px[1].z,px[1].w), h2pk(px[3].z,px[3].w));
            *(uint4*)&Xs[cr][cg * 8 + 0] = s1;
            *(uint4*)&Xs[cr][cg * 8 + 4] = s2;
            s1 = make_uint4(h2pk(pw[0].x,pw[0].y), h2pk(pw[2].x,pw[2].y),
                            h2pk(pw[0].z,pw[0].w), h2pk(pw[2].z,pw[2].w));
            s2 = make_uint4(h2pk(pw[1].x,pw[1].y), h2pk(pw[3].x,pw[3].y),
                            h2pk(pw[1].z,pw[1].w), h2pk(pw[3].z,pw[3].w));
            *(uint4*)&Ws[cr][cg * 8 + 0] = s1;
            *(uint4*)&Ws[cr][cg * 8 + 4] = s2;
        }
        __syncthreads();

        // prefetch kt+1 (LDG spans the mma section)
        if (kt + 1 < Emb / 32) {
            const int kn = (kt + 1) * 32;
            #pragma unroll
            for (int u = 0; u < 4; u++) {
                px[u] = *(const float4*)(Xp + kn + 4 * u);
                pw[u] = *(const float4*)(Wp + kn + 4 * u);
            }
        }

        #pragma unroll
        for (int g = 0; g < 2; g++) {
            unsigned a[2][4];
            #pragma unroll
            for (int mt = 0; mt < 2; mt++) {
                const int rb = 32 * wm + 16 * mt + lg;
                uint2 lo = *(const uint2*)&Xs[rb    ][8 * g + 2 * lt];
                uint2 hi = *(const uint2*)&Xs[rb + 8][8 * g + 2 * lt];
                a[mt][0] = lo.x; a[mt][1] = hi.x; a[mt][2] = lo.y; a[mt][3] = hi.y;
            }
            #pragma unroll
            for (int nt = 0; nt < 8; nt++) {
                const int br = 64 * wn + 8 * nt + lg;
                uint2 bb = *(const uint2*)&Ws[br][8 * g + 2 * lt];
                mma_f16(acc[0][nt], a[0], (const unsigned*)&bb);
                mma_f16(acc[1][nt], a[1], (const unsigned*)&bb);
            }
        }
        __syncthreads();
    }

    // Epilogue: bias, scale, convert fp16, permuted scatter.
    const int bb_ = row0 >> 11;
    const int sb  = row0 & 2047;

    if (which < 2) {
        // Q / K: [B,H,S,D]; d_head = 8nt+2lt -> phys (nt>>1)*16 + 4lt + 2(nt&1)
        #pragma unroll
        for (int nt = 0; nt < 8; nt++) {
            const int ob = o0 + 64 * wn + 8 * nt;
            const int h  = ob >> 6;
            const int dphys = (nt >> 1) * 16 + 4 * lt + 2 * (nt & 1);
            float2 bv2 = *(const float2*)&bias[ob + 2 * lt];
            __half* base = dst + (((size_t)bb_ * NH + h) * Sq) * HD;
            #pragma unroll
            for (int mt = 0; mt < 2; mt++) {
                #pragma unroll
                for (int i = 0; i < 2; i++) {
                    const int s = sb + 32 * wm + 16 * mt + lg + 8 * i;
                    const float v0 = (acc[mt][nt][2 * i    ] + bv2.x) * scale;
                    const float v1 = (acc[mt][nt][2 * i + 1] + bv2.y) * scale;
                    *(uint32_t*)&base[(size_t)s * HD + dphys] = h2pk(v0, v1);
                }
            }
        }
    } else {
        // V: [B,H,D,S]; s within 16-group: idx=8i+lg -> phys 4*(lg>>1)+2i+(lg&1)
        #pragma unroll
        for (int nt = 0; nt < 8; nt++) {
            const int ob = o0 + 64 * wn + 8 * nt;
            const int h  = ob >> 6;
            const int d0 = 8 * nt + 2 * lt;      // within head
            float2 bv2 = *(const float2*)&bias[ob + 2 * lt];
            __half* base = dst + (((size_t)bb_ * NH + h) * HD) * Sq;
            #pragma unroll
            for (int mt = 0; mt < 2; mt++) {
                #pragma unroll
                for (int i = 0; i < 2; i++) {
                    const int sgrp  = sb + 32 * wm + 16 * mt;
                    const int sphys = sgrp + 4 * (lg >> 1) + 2 * i + (lg & 1);
                    base[(size_t)(d0    ) * Sq + sphys] =
                        __float2half_rn(acc[mt][nt][2 * i    ] + bv2.x);
                    base[(size_t)(d0 + 1) * Sq + sphys] =
                        __float2half_rn(acc[mt][nt][2 * i + 1] + bv2.y);
                }
            }
        }
    }
}

// ---------------------------------------------------------------------------
// Kernel 2: fp16 flash attention. q-tile 128, k-tile 64, 8 warps.
// KROW = 144 bytes (36 words == 4 mod 32) -> conflict-free b-fragment LDS.64.
// ---------------------------------------------------------------------------
#define KROW 144
#define KTB  (64 * KROW)          // 9216 bytes per tile
#define ATTN_SMEM (4 * KTB)       // 36864

__global__ __launch_bounds__(256, 2)
void attn_kernel(const float* __restrict__ am,   // [B,1,1,S]
                 const float* __restrict__ dm,   // [B,1,S,S]
                 float* __restrict__ out)        // [B,S,E]
{
    extern __shared__ char smc[];
    char* Kb[2] = { smc,           smc + KTB     };
    char* Vb[2] = { smc + 2 * KTB, smc + 3 * KTB };

    const int tid = threadIdx.x;
    const int w   = tid >> 5;
    const int l   = tid & 31;
    const int lg  = l >> 2;
    const int lt  = l & 3;

    const int q0 = blockIdx.x * 128;
    const int h  = blockIdx.y;
    const int b  = blockIdx.z;

    const char* Kg = (const char*)(g_K + ((size_t)b * NH + h) * Sq * HD);
    const char* Vg = (const char*)(g_V + ((size_t)b * NH + h) * HD * Sq);
    const __half* Qg = g_Q + ((size_t)b * NH + h) * Sq * HD;
    const float* amb = am + (size_t)b * Sq;
    const float* dmb = dm + ((size_t)b * Sq + q0) * Sq;

    const int qr = q0 + 16 * w + lg;

    // Q fragments: 4 k16-groups x {a0,a1,a2,a3}
    unsigned qa[4][4];
    #pragma unroll
    for (int ks = 0; ks < 4; ks++) {
        uint2 r0 = *(const uint2*)((const char*)Qg + ((size_t)(qr    ) * HD + ks * 16) * 2 + 8 * lt);
        uint2 r1 = *(const uint2*)((const char*)Qg + ((size_t)(qr + 8) * HD + ks * 16) * 2 + 8 * lt);
        qa[ks][0] = r0.x; qa[ks][1] = r1.x; qa[ks][2] = r0.y; qa[ks][3] = r1.y;
    }

    float o[8][4];
    #pragma unroll
    for (int nt = 0; nt < 8; nt++)
        #pragma unroll
        for (int j = 0; j < 4; j++) o[nt][j] = 0.f;
    float lr0 = 0.f, lr1 = 0.f;

    // K/V cooperative load: 2 chunks each per tensor per thread
    const int c0r = tid >> 3,          c0j = tid & 7;          // chunks 0..255
    const int c1r = (tid + 256) >> 3,  c1j = tid & 7;          // chunks 256..511

    // prologue: tile 0
    {
        cpa16(Kb[0] + c0r * KROW + c0j * 16, Kg + (size_t)c0r * 128 + c0j * 16);
        cpa16(Kb[0] + c1r * KROW + c1j * 16, Kg + (size_t)c1r * 128 + c1j * 16);
        cpa16(Vb[0] + c0r * KROW + c0j * 16, Vg + (size_t)c0r * 4096 + c0j * 16);
        cpa16(Vb[0] + c1r * KROW + c1j * 16, Vg + (size_t)c1r * 4096 + c1j * 16);
        CP_COMMIT();
    }

    for (int t = 0; t < NT; t++) {
        const int k0 = t * 64;
        const char* Kc = Kb[t & 1];
        const char* Vc = Vb[t & 1];

        CP_WAIT(0);
        __syncthreads();

        // prefetch K/V tile t+1 (wraps harmlessly on last iter)
        {
            const int kn = (t + 1 < NT) ? (k0 + 64) : 0;
            char* Kn = Kb[(t + 1) & 1];
            char* Vn = Vb[(t + 1) & 1];
            cpa16(Kn + c0r * KROW + c0j * 16, Kg + (size_t)(kn + c0r) * 128 + c0j * 16);
            cpa16(Kn + c1r * KROW + c1j * 16, Kg + (size_t)(kn + c1r) * 128 + c1j * 16);
            cpa16(Vn + c0r * KROW + c0j * 16, Vg + (size_t)c0r * 4096 + kn * 2 + c0j * 16);
            cpa16(Vn + c1r * KROW + c1j * 16, Vg + (size_t)c1r * 4096 + kn * 2 + c1j * 16);
            CP_COMMIT();
        }

        // dm prefetch: 16 independent LDG.64 (hidden under QK mma)
        float2 dmv[16];
        #pragma unroll
        for (int nt = 0; nt < 8; nt++) {
            #pragma unroll
            for (int i = 0; i < 2; i++)
                dmv[2 * nt + i] = *(const float2*)
                    &dmb[(size_t)(16 * w + lg + 8 * i) * Sq + k0 + 8 * nt + 2 * lt];
        }

        // S = Q K^T
        float s[8][4];
        #pragma unroll
        for (int nt = 0; nt < 8; nt++)
            #pragma unroll
            for (int j = 0; j < 4; j++) s[nt][j] = 0.f;

        #pragma unroll
        for (int ks = 0; ks < 4; ks++) {
            #pragma unroll
            for (int nt = 0; nt < 8; nt++) {
                uint2 kb = *(const uint2*)(Kc + (8 * nt + lg) * KROW + ks * 32 + 8 * lt);
                mma_f16(s[nt], qa[ks], (const unsigned*)&kb);
            }
        }

        // masks + exp (base-2, log2e pre-folded) + row sums
        float l0 = 0.f, l1 = 0.f;
        #pragma unroll
        for (int nt = 0; nt < 8; nt++) {
            const float2 amv = *(const float2*)&amb[k0 + 8 * nt + 2 * lt];
            float t0, t1;
            t0 = fmaf(dmv[2*nt+0].x, L2E, fmaf(amv.x, L2E, s[nt][0]));
            t1 = fmaf(dmv[2*nt+0].y, L2E, fmaf(amv.y, L2E, s[nt][1]));
            float p0 = ex2f(t0), p1 = ex2f(t1);
            l0 += p0 + p1; s[nt][0] = p0; s[nt][1] = p1;
            t0 = fmaf(dmv[2*nt+1].x, L2E, fmaf(amv.x, L2E, s[nt][2]));
            t1 = fmaf(dmv[2*nt+1].y, L2E, fmaf(amv.y, L2E, s[nt][3]));
            p0 = ex2f(t0); p1 = ex2f(t1);
            l1 += p0 + p1; s[nt][2] = p0; s[nt][3] = p1;
        }
        l0 += __shfl_xor_sync(0xffffffffu, l0, 1);
        l0 += __shfl_xor_sync(0xffffffffu, l0, 2);
        l1 += __shfl_xor_sync(0xffffffffu, l1, 1);
        l1 += __shfl_xor_sync(0xffffffffu, l1, 2);
        lr0 += l0; lr1 += l1;

        // O += P V  (P register-direct: c-frag -> a-frag, zero smem)
        #pragma unroll
        for (int ks = 0; ks < 4; ks++) {
            unsigned pa[4];
            pa[0] = h2pk(s[2*ks  ][0], s[2*ks  ][1]);
            pa[1] = h2pk(s[2*ks  ][2], s[2*ks  ][3]);
            pa[2] = h2pk(s[2*ks+1][0], s[2*ks+1][1]);
            pa[3] = h2pk(s[2*ks+1][2], s[2*ks+1][3]);
            #pragma unroll
            for (int nt = 0; nt < 8; nt++) {
                uint2 vb = *(const uint2*)(Vc + (8 * nt + lg) * KROW + ks * 32 + 8 * lt);
                mma_f16(o[nt], pa, (const unsigned*)&vb);
            }
        }
    }

    // normalize + write out[b][q][h*64 + 8nt+2lt]
    const float inv0 = 1.0f / lr0;
    const float inv1 = 1.0f / lr1;
    #pragma unroll
    for (int nt = 0; nt < 8; nt++) {
        float2 r;
        r.x = o[nt][0] * inv0; r.y = o[nt][1] * inv0;
        *(float2*)&out[((size_t)b * Sq + qr) * Emb + h * HD + 8 * nt + 2 * lt] = r;
        r.x = o[nt][2] * inv1; r.y = o[nt][3] * inv1;
        *(float2*)&out[((size_t)b * Sq + qr + 8) * Emb + h * HD + 8 * nt + 2 * lt] = r;
    }
}

// ---------------------------------------------------------------------------
extern "C" void kernel_launch(void* const* d_in, const int* in_sizes, int n_in,
                              void* d_out, int out_size)
{
    const float* X  = (const float*)d_in[0];
    const float* am = (const float*)d_in[1];
    const float* dm = (const float*)d_in[2];
    const float* Wq = (const float*)d_in[3];
    const float* bq = (const float*)d_in[4];
    const float* Wk = (const float*)d_in[5];
    const float* bk = (const float*)d_in[6];
    const float* Wv = (const float*)d_in[7];
    const float* bv = (const float*)d_in[8];
    float* out = (float*)d_out;

    qkv_kernel<<<dim3(18, 64), 256>>>(X, Wq, bq, Wk, bk, Wv, bv);

    cudaFuncSetAttribute(attn_kernel,
                         cudaFuncAttributeMaxDynamicSharedMemorySize,
                         ATTN_SMEM);
    attn_kernel<<<dim3(Sq / 128, NH, Bsz), 256, ATTN_SMEM>>>(am, dm, out);
}

// round 12
// speedup vs baseline: 1.3030x; 1.3030x over previous
#include <cuda_runtime.h>
#include <cuda_fp16.h>
#include <cstdint>

#define Bsz 4
#define Sq  2048
#define Emb 768
#define NH  12
#define HD  64
#define NT  (Sq / 64)            // 32 k-tiles of 64 keys
#define L2E 1.4426950408889634f

// Q, K: [B,H,S,D] half, D pair-interleaved within 16-groups.
// V: [B,H,D,S] half, S pair-interleaved within 16-groups.
// Q pre-scaled by 0.125 * log2(e).
__device__ __half g_Q[(size_t)Bsz * NH * Sq * HD];
__device__ __half g_K[(size_t)Bsz * NH * Sq * HD];
__device__ __half g_V[(size_t)Bsz * NH * Sq * HD];

// ---------------------------------------------------------------------------
// helpers
// ---------------------------------------------------------------------------
__device__ __forceinline__ unsigned h2pk(float lo, float hi) {
    unsigned r;
    asm("cvt.rn.f16x2.f32 %0, %1, %2;" : "=r"(r) : "f"(hi), "f"(lo));
    return r;
}
__device__ __forceinline__ float ex2f(float x) {
    float r;
    asm("ex2.approx.f32 %0, %1;" : "=f"(r) : "f"(x));
    return r;
}
__device__ __forceinline__ unsigned ex2h2(unsigned x) {
    unsigned r;
    asm("ex2.approx.f16x2 %0, %1;" : "=r"(r) : "r"(x));
    return r;
}
__device__ __forceinline__ void mma_f16(float* d, const unsigned* a, const unsigned* b) {
    asm volatile(
        "mma.sync.aligned.m16n8k16.row.col.f32.f16.f16.f32 "
        "{%0,%1,%2,%3}, {%4,%5,%6,%7}, {%8,%9}, {%0,%1,%2,%3};"
        : "+f"(d[0]), "+f"(d[1]), "+f"(d[2]), "+f"(d[3])
        : "r"(a[0]), "r"(a[1]), "r"(a[2]), "r"(a[3]), "r"(b[0]), "r"(b[1]));
}
__device__ __forceinline__ void cpa16(void* s, const void* g) {
    unsigned sa = (unsigned)__cvta_generic_to_shared(s);
    asm volatile("cp.async.cg.shared.global [%0], [%1], 16;" :: "r"(sa), "l"(g));
}
#define CP_COMMIT()  asm volatile("cp.async.commit_group;")
#define CP_WAIT(N)   asm volatile("cp.async.wait_group %0;" :: "n"(N))

// ---------------------------------------------------------------------------
// Kernel 1: fused QKV projection, fp16 mma (fp32 accum). (R9 proven version.)
// ---------------------------------------------------------------------------
#define XW 24   // words per smem row (48 halves = 96B); 24 % 32 -> conflict-free phases

__global__ __launch_bounds__(256, 2)
void qkv_kernel(const float* __restrict__ X,
                const float* __restrict__ Wq, const float* __restrict__ bq,
                const float* __restrict__ Wk, const float* __restrict__ bk,
                const float* __restrict__ Wv, const float* __restrict__ bv)
{
    __shared__ uint32_t Xs[128][XW];
    __shared__ uint32_t Ws[128][XW];

    const int tid = threadIdx.x;
    const int w   = tid >> 5;
    const int l   = tid & 31;
    const int wm  = w >> 1;
    const int wn  = w & 1;
    const int lg  = l >> 2;
    const int lt  = l & 3;

    const int bx    = blockIdx.x;
    const int row0  = blockIdx.y * 128;
    const int which = bx / 6;
    const int o0    = (bx % 6) * 128;

    const float* W    = (which == 0) ? Wq : (which == 1) ? Wk : Wv;
    const float* bias = (which == 0) ? bq : (which == 1) ? bk : bv;
    __half*      dst  = (which == 0) ? g_Q : (which == 1) ? g_K : g_V;
    const float scale = (which == 0) ? (0.125f * L2E) : 1.0f;

    float acc[2][8][4];
    #pragma unroll
    for (int mt = 0; mt < 2; mt++)
        #pragma unroll
        for (int nt = 0; nt < 8; nt++)
            #pragma unroll
            for (int j = 0; j < 4; j++) acc[mt][nt][j] = 0.f;

    const int cr = tid >> 1;           // row 0..127
    const int cg = tid & 1;            // k16-group within k-tile

    for (int kt = 0; kt < Emb / 32; kt++) {
        const int k0 = kt * 32 + cg * 16;
        {
            float4 u0 = *(const float4*)&X[(size_t)(row0 + cr) * Emb + k0 + 0];
            float4 u1 = *(const float4*)&X[(size_t)(row0 + cr) * Emb + k0 + 4];
            float4 u2 = *(const float4*)&X[(size_t)(row0 + cr) * Emb + k0 + 8];
            float4 u3 = *(const float4*)&X[(size_t)(row0 + cr) * Emb + k0 + 12];
            uint4 s1 = make_uint4(h2pk(u0.x,u0.y), h2pk(u2.x,u2.y),
                                  h2pk(u0.z,u0.w), h2pk(u2.z,u2.w));
            uint4 s2 = make_uint4(h2pk(u1.x,u1.y), h2pk(u3.x,u3.y),
                                  h2pk(u1.z,u1.w), h2pk(u3.z,u3.w));
            *(uint4*)&Xs[cr][cg * 8 + 0] = s1;
            *(uint4*)&Xs[cr][cg * 8 + 4] = s2;
            u0 = *(const float4*)&W[(size_t)(o0 + cr) * Emb + k0 + 0];
            u1 = *(const float4*)&W[(size_t)(o0 + cr) * Emb + k0 + 4];
            u2 = *(const float4*)&W[(size_t)(o0 + cr) * Emb + k0 + 8];
            u3 = *(const float4*)&W[(size_t)(o0 + cr) * Emb + k0 + 12];
            s1 = make_uint4(h2pk(u0.x,u0.y), h2pk(u2.x,u2.y),
                            h2pk(u0.z,u0.w), h2pk(u2.z,u2.w));
            s2 = make_uint4(h2pk(u1.x,u1.y), h2pk(u3.x,u3.y),
                            h2pk(u1.z,u1.w), h2pk(u3.z,u3.w));
            *(uint4*)&Ws[cr][cg * 8 + 0] = s1;
            *(uint4*)&Ws[cr][cg * 8 + 4] = s2;
        }
        __syncthreads();

        #pragma unroll
        for (int g = 0; g < 2; g++) {
            unsigned a[2][4];
            #pragma unroll
            for (int mt = 0; mt < 2; mt++) {
                const int rb = 32 * wm + 16 * mt + lg;
                uint2 lo = *(const uint2*)&Xs[rb    ][8 * g + 2 * lt];
                uint2 hi = *(const uint2*)&Xs[rb + 8][8 * g + 2 * lt];
                a[mt][0] = lo.x; a[mt][1] = hi.x; a[mt][2] = lo.y; a[mt][3] = hi.y;
            }
            #pragma unroll
            for (int nt = 0; nt < 8; nt++) {
                const int br = 64 * wn + 8 * nt + lg;
                uint2 bb = *(const uint2*)&Ws[br][8 * g + 2 * lt];
                mma_f16(acc[0][nt], a[0], (const unsigned*)&bb);
                mma_f16(acc[1][nt], a[1], (const unsigned*)&bb);
            }
        }
        __syncthreads();
    }

    const int bb_ = row0 >> 11;
    const int sb  = row0 & 2047;

    if (which < 2) {
        // Q / K: [B,H,S,D]; d = 8nt+2lt -> phys (nt>>1)*16 + 4lt + 2(nt&1)
        #pragma unroll
        for (int nt = 0; nt < 8; nt++) {
            const int ob = o0 + 64 * wn + 8 * nt;
            const int h  = ob >> 6;
            const int dphys = (nt >> 1) * 16 + 4 * lt + 2 * (nt & 1);
            float2 bv2 = *(const float2*)&bias[ob + 2 * lt];
            __half* base = dst + (((size_t)bb_ * NH + h) * Sq) * HD;
            #pragma unroll
            for (int mt = 0; mt < 2; mt++) {
                #pragma unroll
                for (int i = 0; i < 2; i++) {
                    const int s = sb + 32 * wm + 16 * mt + lg + 8 * i;
                    const float v0 = (acc[mt][nt][2 * i    ] + bv2.x) * scale;
                    const float v1 = (acc[mt][nt][2 * i + 1] + bv2.y) * scale;
                    *(uint32_t*)&base[(size_t)s * HD + dphys] = h2pk(v0, v1);
                }
            }
        }
    } else {
        // V: [B,H,D,S]; s within 16-group: idx=8i+lg -> phys 4*(lg>>1)+2i+(lg&1)
        #pragma unroll
        for (int nt = 0; nt < 8; nt++) {
            const int ob = o0 + 64 * wn + 8 * nt;
            const int h  = ob >> 6;
            const int d0 = 8 * nt + 2 * lt;
            float2 bv2 = *(const float2*)&bias[ob + 2 * lt];
            __half* base = dst + (((size_t)bb_ * NH + h) * HD) * Sq;
            #pragma unroll
            for (int mt = 0; mt < 2; mt++) {
                #pragma unroll
                for (int i = 0; i < 2; i++) {
                    const int sgrp  = sb + 32 * wm + 16 * mt;
                    const int sphys = sgrp + 4 * (lg >> 1) + 2 * i + (lg & 1);
                    base[(size_t)(d0    ) * Sq + sphys] =
                        __float2half_rn(acc[mt][nt][2 * i    ] + bv2.x);
                    base[(size_t)(d0 + 1) * Sq + sphys] =
                        __float2half_rn(acc[mt][nt][2 * i + 1] + bv2.y);
                }
            }
        }
    }
}

// ---------------------------------------------------------------------------
// Kernel 2: fp16 flash attention, m32 warp tiles.
// 128 thr/CTA (4 warps x 32 q-rows), 2 CTAs/SM. KROW=160 (phase-conflict-free).
// Row-sum via ones-column in V (nt=8); exp via ex2.approx.f16x2.
// ---------------------------------------------------------------------------
#define KROW 160
#define KTBK (64 * KROW)          // 10240
#define KTBV (72 * KROW)          // 11520 (64 data rows + 8 ones/zero rows)
#define ATTN_SMEM (2 * KTBK + 2 * KTBV)   // 43520

__global__ __launch_bounds__(128, 2)
void attn_kernel(const float* __restrict__ am,   // [B,1,1,S]
                 const float* __restrict__ dm,   // [B,1,S,S]
                 float* __restrict__ out)        // [B,S,E]
{
    extern __shared__ char smc[];
    char* Kb[2] = { smc,            smc + KTBK        };
    char* Vb[2] = { smc + 2 * KTBK, smc + 2 * KTBK + KTBV };

    const int tid = threadIdx.x;
    const int w   = tid >> 5;
    const int l   = tid & 31;
    const int lg  = l >> 2;
    const int lt  = l & 3;

    const int q0 = blockIdx.x * 128;
    const int h  = blockIdx.y;
    const int b  = blockIdx.z;

    const char* Kg = (const char*)(g_K + ((size_t)b * NH + h) * Sq * HD);
    const char* Vg = (const char*)(g_V + ((size_t)b * NH + h) * HD * Sq);
    const __half* Qg = g_Q + ((size_t)b * NH + h) * Sq * HD;
    const float* amb = am + (size_t)b * Sq;
    const float* dmb = dm + ((size_t)b * Sq + q0) * Sq;

    const int qr = q0 + 32 * w + lg;   // this thread's base q-row (of 4: +0,+8,+16,+24)

    // Q fragments: 4 k16-groups x 8 regs (regs 0-3 rows +0/+8, regs 4-7 rows +16/+24)
    unsigned qa[4][8];
    #pragma unroll
    for (int ks = 0; ks < 4; ks++) {
        uint2 u0 = *(const uint2*)((const char*)Qg + ((size_t)(qr     ) * HD + ks * 16) * 2 + 8 * lt);
        uint2 u1 = *(const uint2*)((const char*)Qg + ((size_t)(qr +  8) * HD + ks * 16) * 2 + 8 * lt);
        uint2 u2 = *(const uint2*)((const char*)Qg + ((size_t)(qr + 16) * HD + ks * 16) * 2 + 8 * lt);
        uint2 u3 = *(const uint2*)((const char*)Qg + ((size_t)(qr + 24) * HD + ks * 16) * 2 + 8 * lt);
        qa[ks][0] = u0.x; qa[ks][1] = u1.x; qa[ks][2] = u0.y; qa[ks][3] = u1.y;
        qa[ks][4] = u2.x; qa[ks][5] = u3.x; qa[ks][6] = u2.y; qa[ks][7] = u3.y;
    }

    float o[9][8];
    #pragma unroll
    for (int nt = 0; nt < 9; nt++)
        #pragma unroll
        for (int j = 0; j < 8; j++) o[nt][j] = 0.f;

    // ones-column init: V rows 64-71, both buffers (row 64 = 1.0 over 64 keys)
    for (int i = tid; i < 320; i += 128) {
        const int r  = 64 + i / 40;
        const int wd = i % 40;
        const unsigned v = (r == 64 && wd < 32) ? 0x3C003C00u : 0u;
        *(unsigned*)(Vb[0] + r * KROW + wd * 4) = v;
        *(unsigned*)(Vb[1] + r * KROW + wd * 4) = v;
    }

    // prologue: K/V tile 0 (4 chunks each per thread)
    #pragma unroll
    for (int i = 0; i < 4; i++) {
        const int c = tid + 128 * i;
        const int r = c >> 3, j = c & 7;
        cpa16(Kb[0] + r * KROW + j * 16, Kg + (size_t)r * 128 + j * 16);
        cpa16(Vb[0] + r * KROW + j * 16, Vg + (size_t)r * 4096 + j * 16);
    }
    CP_COMMIT();

    for (int t = 0; t < NT; t++) {
        const int k0 = t * 64;
        const char* Kc = Kb[t & 1];
        const char* Vc = Vb[t & 1];

        CP_WAIT(0);
        __syncthreads();

        // prefetch K/V tile t+1 (wraps harmlessly)
        {
            const int kn = (t + 1 < NT) ? (k0 + 64) : 0;
            char* Kn = Kb[(t + 1) & 1];
            char* Vn = Vb[(t + 1) & 1];
            #pragma unroll
            for (int i = 0; i < 4; i++) {
                const int c = tid + 128 * i;
                const int r = c >> 3, j = c & 7;
                cpa16(Kn + r * KROW + j * 16, Kg + (size_t)(kn + r) * 128 + j * 16);
                cpa16(Vn + r * KROW + j * 16, Vg + (size_t)r * 4096 + kn * 2 + j * 16);
            }
            CP_COMMIT();
        }

        // S = Q K^T : one b-frag LDS.64 serves both m16 halves
        float s[8][8];
        #pragma unroll
        for (int nt = 0; nt < 8; nt++)
            #pragma unroll
            for (int j = 0; j < 8; j++) s[nt][j] = 0.f;

        #pragma unroll
        for (int ks = 0; ks < 4; ks++) {
            #pragma unroll
            for (int nt = 0; nt < 8; nt++) {
                uint2 kb = *(const uint2*)(Kc + (8 * nt + lg) * KROW + ks * 32 + 8 * lt);
                mma_f16(&s[nt][0], &qa[ks][0], (const unsigned*)&kb);
                mma_f16(&s[nt][4], &qa[ks][4], (const unsigned*)&kb);
            }
        }

        // epilogue per m16 half: masks + f16x2 exp -> PV a-frags directly
        unsigned pa[2][4][4];
        #pragma unroll
        for (int h2 = 0; h2 < 2; h2++) {
            const int ra = 32 * w + 16 * h2 + lg;   // local q-row (pair base)
            float2 dmv[16];
            #pragma unroll
            for (int nt = 0; nt < 8; nt++) {
                dmv[2*nt  ] = *(const float2*)&dmb[(size_t)(ra    ) * Sq + k0 + 8 * nt + 2 * lt];
                dmv[2*nt+1] = *(const float2*)&dmb[(size_t)(ra + 8) * Sq + k0 + 8 * nt + 2 * lt];
            }
            #pragma unroll
            for (int nt = 0; nt < 8; nt++) {
                const float2 amv = *(const float2*)&amb[k0 + 8 * nt + 2 * lt];
                const float t00 = fmaf(dmv[2*nt  ].x, L2E, fmaf(amv.x, L2E, s[nt][4*h2+0]));
                const float t01 = fmaf(dmv[2*nt  ].y, L2E, fmaf(amv.y, L2E, s[nt][4*h2+1]));
                const float t10 = fmaf(dmv[2*nt+1].x, L2E, fmaf(amv.x, L2E, s[nt][4*h2+2]));
                const float t11 = fmaf(dmv[2*nt+1].y, L2E, fmaf(amv.y, L2E, s[nt][4*h2+3]));
                pa[h2][nt >> 1][(nt & 1) * 2 + 0] = ex2h2(h2pk(t00, t01));
                pa[h2][nt >> 1][(nt & 1) * 2 + 1] = ex2h2(h2pk(t10, t11));
            }
        }

        // O += P V ; nt=8 is the ones-column (row-sum) group
        #pragma unroll
        for (int ks = 0; ks < 4; ks++) {
            #pragma unroll
            for (int nt = 0; nt < 9; nt++) {
                uint2 vb = *(const uint2*)(Vc + (8 * nt + lg) * KROW + ks * 32 + 8 * lt);
                mma_f16(&o[nt][0], pa[0][ks], (const unsigned*)&vb);
                mma_f16(&o[nt][4], pa[1][ks], (const unsigned*)&vb);
            }
        }
    }

    // row sums live in o[8] col 0 (lanes lt==0); broadcast and normalize
    const unsigned FULL = 0xffffffffu;
    const float inv0 = 1.0f / __shfl_sync(FULL, o[8][0], l & 28);
    const float inv1 = 1.0f / __shfl_sync(FULL, o[8][2], l & 28);
    const float inv2 = 1.0f / __shfl_sync(FULL, o[8][4], l & 28);
    const float inv3 = 1.0f / __shfl_sync(FULL, o[8][6], l & 28);

    #pragma unroll
    for (int nt = 0; nt < 8; nt++) {
        const int col = h * HD + 8 * nt + 2 * lt;
        float2 r;
        r.x = o[nt][0] * inv0; r.y = o[nt][1] * inv0;
        *(float2*)&out[((size_t)b * Sq + qr     ) * Emb + col] = r;
        r.x = o[nt][2] * inv1; r.y = o[nt][3] * inv1;
        *(float2*)&out[((size_t)b * Sq + qr +  8) * Emb + col] = r;
        r.x = o[nt][4] * inv2; r.y = o[nt][5] * inv2;
        *(float2*)&out[((size_t)b * Sq + qr + 16) * Emb + col] = r;
        r.x = o[nt][6] * inv3; r.y = o[nt][7] * inv3;
        *(float2*)&out[((size_t)b * Sq + qr + 24) * Emb + col] = r;
    }
}

// ---------------------------------------------------------------------------
extern "C" void kernel_launch(void* const* d_in, const int* in_sizes, int n_in,
                              void* d_out, int out_size)
{
    const float* X  = (const float*)d_in[0];
    const float* am = (const float*)d_in[1];
    const float* dm = (const float*)d_in[2];
    const float* Wq = (const float*)d_in[3];
    const float* bq = (const float*)d_in[4];
    const float* Wk = (const float*)d_in[5];
    const float* bk = (const float*)d_in[6];
    const float* Wv = (const float*)d_in[7];
    const float* bv = (const float*)d_in[8];
    float* out = (float*)d_out;

    qkv_kernel<<<dim3(18, 64), 256>>>(X, Wq, bq, Wk, bk, Wv, bv);

    cudaFuncSetAttribute(attn_kernel,
                         cudaFuncAttributeMaxDynamicSharedMemorySize,
                         ATTN_SMEM);
    attn_kernel<<<dim3(Sq / 128, NH, Bsz), 128, ATTN_SMEM>>>(am, dm, out);
}

// round 13
// speedup vs baseline: 1.3063x; 1.0025x over previous
#include <cuda_runtime.h>
#include <cuda_fp16.h>
#include <cstdint>

#define Bsz 4
#define Sq  2048
#define Emb 768
#define NH  12
#define HD  64
#define NT  (Sq / 64)            // 32 k-tiles of 64 keys
#define L2E 1.4426950408889634f

// Q, K: [B,H,S,D] half, D pair-interleaved within 16-groups.
// V: [B,H,D,S] half, S pair-interleaved within 16-groups.
// Q pre-scaled by 0.125 * log2(e).
__device__ __half g_Q[(size_t)Bsz * NH * Sq * HD];
__device__ __half g_K[(size_t)Bsz * NH * Sq * HD];
__device__ __half g_V[(size_t)Bsz * NH * Sq * HD];

// ---------------------------------------------------------------------------
// helpers
// ---------------------------------------------------------------------------
__device__ __forceinline__ unsigned h2pk(float lo, float hi) {
    unsigned r;
    asm("cvt.rn.f16x2.f32 %0, %1, %2;" : "=r"(r) : "f"(hi), "f"(lo));
    return r;
}
__device__ __forceinline__ float ex2f(float x) {
    float r;
    asm("ex2.approx.f32 %0, %1;" : "=f"(r) : "f"(x));
    return r;
}
__device__ __forceinline__ void mma_f16(float* d, const unsigned* a, const unsigned* b) {
    asm volatile(
        "mma.sync.aligned.m16n8k16.row.col.f32.f16.f16.f32 "
        "{%0,%1,%2,%3}, {%4,%5,%6,%7}, {%8,%9}, {%0,%1,%2,%3};"
        : "+f"(d[0]), "+f"(d[1]), "+f"(d[2]), "+f"(d[3])
        : "r"(a[0]), "r"(a[1]), "r"(a[2]), "r"(a[3]), "r"(b[0]), "r"(b[1]));
}
__device__ __forceinline__ void cpa16(void* s, const void* g) {
    unsigned sa = (unsigned)__cvta_generic_to_shared(s);
    asm volatile("cp.async.cg.shared.global [%0], [%1], 16;" :: "r"(sa), "l"(g));
}
#define CP_COMMIT()  asm volatile("cp.async.commit_group;")
#define CP_WAIT(N)   asm volatile("cp.async.wait_group %0;" :: "n"(N))

// ---------------------------------------------------------------------------
// Kernel 1: fused QKV projection, fp16 mma (fp32 accum). (Proven R9 version.)
// ---------------------------------------------------------------------------
#define XW 24

__global__ __launch_bounds__(256, 2)
void qkv_kernel(const float* __restrict__ X,
                const float* __restrict__ Wq, const float* __restrict__ bq,
                const float* __restrict__ Wk, const float* __restrict__ bk,
                const float* __restrict__ Wv, const float* __restrict__ bv)
{
    __shared__ uint32_t Xs[128][XW];
    __shared__ uint32_t Ws[128][XW];

    const int tid = threadIdx.x;
    const int w   = tid >> 5;
    const int l   = tid & 31;
    const int wm  = w >> 1;
    const int wn  = w & 1;
    const int lg  = l >> 2;
    const int lt  = l & 3;

    const int bx    = blockIdx.x;
    const int row0  = blockIdx.y * 128;
    const int which = bx / 6;
    const int o0    = (bx % 6) * 128;

    const float* W    = (which == 0) ? Wq : (which == 1) ? Wk : Wv;
    const float* bias = (which == 0) ? bq : (which == 1) ? bk : bv;
    __half*      dst  = (which == 0) ? g_Q : (which == 1) ? g_K : g_V;
    const float scale = (which == 0) ? (0.125f * L2E) : 1.0f;

    float acc[2][8][4];
    #pragma unroll
    for (int mt = 0; mt < 2; mt++)
        #pragma unroll
        for (int nt = 0; nt < 8; nt++)
            #pragma unroll
            for (int j = 0; j < 4; j++) acc[mt][nt][j] = 0.f;

    const int cr = tid >> 1;
    const int cg = tid & 1;

    for (int kt = 0; kt < Emb / 32; kt++) {
        const int k0 = kt * 32 + cg * 16;
        {
            float4 u0 = *(const float4*)&X[(size_t)(row0 + cr) * Emb + k0 + 0];
            float4 u1 = *(const float4*)&X[(size_t)(row0 + cr) * Emb + k0 + 4];
            float4 u2 = *(const float4*)&X[(size_t)(row0 + cr) * Emb + k0 + 8];
            float4 u3 = *(const float4*)&X[(size_t)(row0 + cr) * Emb + k0 + 12];
            uint4 s1 = make_uint4(h2pk(u0.x,u0.y), h2pk(u2.x,u2.y),
                                  h2pk(u0.z,u0.w), h2pk(u2.z,u2.w));
            uint4 s2 = make_uint4(h2pk(u1.x,u1.y), h2pk(u3.x,u3.y),
                                  h2pk(u1.z,u1.w), h2pk(u3.z,u3.w));
            *(uint4*)&Xs[cr][cg * 8 + 0] = s1;
            *(uint4*)&Xs[cr][cg * 8 + 4] = s2;
            u0 = *(const float4*)&W[(size_t)(o0 + cr) * Emb + k0 + 0];
            u1 = *(const float4*)&W[(size_t)(o0 + cr) * Emb + k0 + 4];
            u2 = *(const float4*)&W[(size_t)(o0 + cr) * Emb + k0 + 8];
            u3 = *(const float4*)&W[(size_t)(o0 + cr) * Emb + k0 + 12];
            s1 = make_uint4(h2pk(u0.x,u0.y), h2pk(u2.x,u2.y),
                            h2pk(u0.z,u0.w), h2pk(u2.z,u2.w));
            s2 = make_uint4(h2pk(u1.x,u1.y), h2pk(u3.x,u3.y),
                            h2pk(u1.z,u1.w), h2pk(u3.z,u3.w));
            *(uint4*)&Ws[cr][cg * 8 + 0] = s1;
            *(uint4*)&Ws[cr][cg * 8 + 4] = s2;
        }
        __syncthreads();

        #pragma unroll
        for (int g = 0; g < 2; g++) {
            unsigned a[2][4];
            #pragma unroll
            for (int mt = 0; mt < 2; mt++) {
                const int rb = 32 * wm + 16 * mt + lg;
                uint2 lo = *(const uint2*)&Xs[rb    ][8 * g + 2 * lt];
                uint2 hi = *(const uint2*)&Xs[rb + 8][8 * g + 2 * lt];
                a[mt][0] = lo.x; a[mt][1] = hi.x; a[mt][2] = lo.y; a[mt][3] = hi.y;
            }
            #pragma unroll
            for (int nt = 0; nt < 8; nt++) {
                const int br = 64 * wn + 8 * nt + lg;
                uint2 bb = *(const uint2*)&Ws[br][8 * g + 2 * lt];
                mma_f16(acc[0][nt], a[0], (const unsigned*)&bb);
                mma_f16(acc[1][nt], a[1], (const unsigned*)&bb);
            }
        }
        __syncthreads();
    }

    const int bb_ = row0 >> 11;
    const int sb  = row0 & 2047;

    if (which < 2) {
        #pragma unroll
        for (int nt = 0; nt < 8; nt++) {
            const int ob = o0 + 64 * wn + 8 * nt;
            const int h  = ob >> 6;
            const int dphys = (nt >> 1) * 16 + 4 * lt + 2 * (nt & 1);
            float2 bv2 = *(const float2*)&bias[ob + 2 * lt];
            __half* base = dst + (((size_t)bb_ * NH + h) * Sq) * HD;
            #pragma unroll
            for (int mt = 0; mt < 2; mt++) {
                #pragma unroll
                for (int i = 0; i < 2; i++) {
                    const int s = sb + 32 * wm + 16 * mt + lg + 8 * i;
                    const float v0 = (acc[mt][nt][2 * i    ] + bv2.x) * scale;
                    const float v1 = (acc[mt][nt][2 * i + 1] + bv2.y) * scale;
                    *(uint32_t*)&base[(size_t)s * HD + dphys] = h2pk(v0, v1);
                }
            }
        }
    } else {
        #pragma unroll
        for (int nt = 0; nt < 8; nt++) {
            const int ob = o0 + 64 * wn + 8 * nt;
            const int h  = ob >> 6;
            const int d0 = 8 * nt + 2 * lt;
            float2 bv2 = *(const float2*)&bias[ob + 2 * lt];
            __half* base = dst + (((size_t)bb_ * NH + h) * HD) * Sq;
            #pragma unroll
            for (int mt = 0; mt < 2; mt++) {
                #pragma unroll
                for (int i = 0; i < 2; i++) {
                    const int sgrp  = sb + 32 * wm + 16 * mt;
                    const int sphys = sgrp + 4 * (lg >> 1) + 2 * i + (lg & 1);
                    base[(size_t)(d0    ) * Sq + sphys] =
                        __float2half_rn(acc[mt][nt][2 * i    ] + bv2.x);
                    base[(size_t)(d0 + 1) * Sq + sphys] =
                        __float2half_rn(acc[mt][nt][2 * i + 1] + bv2.y);
                }
            }
        }
    }
}

// ---------------------------------------------------------------------------
// Kernel 2: fp16 flash attention, m32 warp tiles, 32-key half-passes.
// 128 thr/CTA (4 warps x 32 q-rows), 2 CTAs/SM, KROW=160.
// fp32 exp; fp32 row-sums; P packed fp16 register-direct into PV.
// ---------------------------------------------------------------------------
#define KROW 160
#define KTB  (64 * KROW)          // 10240
#define ATTN_SMEM (4 * KTB)       // 40960

__global__ __launch_bounds__(128, 2)
void attn_kernel(const float* __restrict__ am,   // [B,1,1,S]
                 const float* __restrict__ dm,   // [B,1,S,S]
                 float* __restrict__ out)        // [B,S,E]
{
    extern __shared__ char smc[];
    char* Kb[2] = { smc,           smc + KTB     };
    char* Vb[2] = { smc + 2 * KTB, smc + 3 * KTB };

    const int tid = threadIdx.x;
    const int w   = tid >> 5;
    const int l   = tid & 31;
    const int lg  = l >> 2;
    const int lt  = l & 3;

    const int q0 = blockIdx.x * 128;
    const int h  = blockIdx.y;
    const int b  = blockIdx.z;

    const char* Kg = (const char*)(g_K + ((size_t)b * NH + h) * Sq * HD);
    const char* Vg = (const char*)(g_V + ((size_t)b * NH + h) * HD * Sq);
    const __half* Qg = g_Q + ((size_t)b * NH + h) * Sq * HD;
    const float* amb = am + (size_t)b * Sq;
    const float* dmb = dm + ((size_t)b * Sq + q0) * Sq;

    const int qr = q0 + 32 * w + lg;   // rows handled: qr, +8, +16, +24

    // Q fragments: 4 k16-groups x 8 regs (0-3: rows +0/+8; 4-7: rows +16/+24)
    unsigned qa[4][8];
    #pragma unroll
    for (int ks = 0; ks < 4; ks++) {
        uint2 u0 = *(const uint2*)((const char*)Qg + ((size_t)(qr     ) * HD + ks * 16) * 2 + 8 * lt);
        uint2 u1 = *(const uint2*)((const char*)Qg + ((size_t)(qr +  8) * HD + ks * 16) * 2 + 8 * lt);
        uint2 u2 = *(const uint2*)((const char*)Qg + ((size_t)(qr + 16) * HD + ks * 16) * 2 + 8 * lt);
        uint2 u3 = *(const uint2*)((const char*)Qg + ((size_t)(qr + 24) * HD + ks * 16) * 2 + 8 * lt);
        qa[ks][0] = u0.x; qa[ks][1] = u1.x; qa[ks][2] = u0.y; qa[ks][3] = u1.y;
        qa[ks][4] = u2.x; qa[ks][5] = u3.x; qa[ks][6] = u2.y; qa[ks][7] = u3.y;
    }

    float o[8][8];
    #pragma unroll
    for (int nt = 0; nt < 8; nt++)
        #pragma unroll
        for (int j = 0; j < 8; j++) o[nt][j] = 0.f;
    float lr[4] = {0.f, 0.f, 0.f, 0.f};

    // prologue: K/V tile 0 (4 chunks each per thread)
    #pragma unroll
    for (int i = 0; i < 4; i++) {
        const int c = tid + 128 * i;
        const int r = c >> 3, j = c & 7;
        cpa16(Kb[0] + r * KROW + j * 16, Kg + (size_t)r * 128 + j * 16);
        cpa16(Vb[0] + r * KROW + j * 16, Vg + (size_t)r * 4096 + j * 16);
    }
    CP_COMMIT();

    for (int t = 0; t < NT; t++) {
        const int k0 = t * 64;
        const char* Kc = Kb[t & 1];
        const char* Vc = Vb[t & 1];

        CP_WAIT(0);
        __syncthreads();

        // prefetch K/V tile t+1 (wraps harmlessly)
        {
            const int kn = (t + 1 < NT) ? (k0 + 64) : 0;
            char* Kn = Kb[(t + 1) & 1];
            char* Vn = Vb[(t + 1) & 1];
            #pragma unroll
            for (int i = 0; i < 4; i++) {
                const int c = tid + 128 * i;
                const int r = c >> 3, j = c & 7;
                cpa16(Kn + r * KROW + j * 16, Kg + (size_t)(kn + r) * 128 + j * 16);
                cpa16(Vn + r * KROW + j * 16, Vg + (size_t)r * 4096 + kn * 2 + j * 16);
            }
            CP_COMMIT();
        }

        // two 32-key half-passes
        #pragma unroll
        for (int kh = 0; kh < 2; kh++) {
            const int kc = k0 + 32 * kh + 2 * lt;   // this thread's key pair base

            // dm prefetch for this half (hidden under QK mma below)
            float2 dmv[16];
            #pragma unroll
            for (int h2 = 0; h2 < 2; h2++) {
                const int ra = 32 * w + 16 * h2 + lg;
                #pragma unroll
                for (int nt = 0; nt < 4; nt++) {
                    dmv[8*h2 + 2*nt    ] = *(const float2*)&dmb[(size_t)(ra    ) * Sq + kc + 8 * nt];
                    dmv[8*h2 + 2*nt + 1] = *(const float2*)&dmb[(size_t)(ra + 8) * Sq + kc + 8 * nt];
                }
            }

            // S = Q K^T for keys [32kh, 32kh+32)
            float s[4][8];
            #pragma unroll
            for (int nt = 0; nt < 4; nt++)
                #pragma unroll
                for (int j = 0; j < 8; j++) s[nt][j] = 0.f;

            #pragma unroll
            for (int ks = 0; ks < 4; ks++) {
                #pragma unroll
                for (int nt = 0; nt < 4; nt++) {
                    uint2 kb = *(const uint2*)(Kc + (32 * kh + 8 * nt + lg) * KROW + ks * 32 + 8 * lt);
                    mma_f16(&s[nt][0], &qa[ks][0], (const unsigned*)&kb);
                    mma_f16(&s[nt][4], &qa[ks][4], (const unsigned*)&kb);
                }
            }

            // masks + fp32 exp + fp32 row sums; pack P as PV a-frags
            unsigned pa[2][2][4];
            #pragma unroll
            for (int h2 = 0; h2 < 2; h2++) {
                #pragma unroll
                for (int nt = 0; nt < 4; nt++) {
                    const float2 amv = *(const float2*)&amb[kc + 8 * nt];
                    const float2 d0 = dmv[8*h2 + 2*nt    ];
                    const float2 d1 = dmv[8*h2 + 2*nt + 1];
                    const float p00 = ex2f(fmaf(d0.x, L2E, fmaf(amv.x, L2E, s[nt][4*h2+0])));
                    const float p01 = ex2f(fmaf(d0.y, L2E, fmaf(amv.y, L2E, s[nt][4*h2+1])));
                    const float p10 = ex2f(fmaf(d1.x, L2E, fmaf(amv.x, L2E, s[nt][4*h2+2])));
                    const float p11 = ex2f(fmaf(d1.y, L2E, fmaf(amv.y, L2E, s[nt][4*h2+3])));
                    lr[2*h2    ] += p00 + p01;
                    lr[2*h2 + 1] += p10 + p11;
                    pa[h2][nt >> 1][(nt & 1) * 2 + 0] = h2pk(p00, p01);
                    pa[h2][nt >> 1][(nt & 1) * 2 + 1] = h2pk(p10, p11);
                }
            }

            // O += P V for this key half
            #pragma unroll
            for (int ks2 = 0; ks2 < 2; ks2++) {
                const int kso = (2 * kh + ks2) * 32;
                #pragma unroll
                for (int nt = 0; nt < 8; nt++) {
                    uint2 vb = *(const uint2*)(Vc + (8 * nt + lg) * KROW + kso + 8 * lt);
                    mma_f16(&o[nt][0], pa[0][ks2], (const unsigned*)&vb);
                    mma_f16(&o[nt][4], pa[1][ks2], (const unsigned*)&vb);
                }
            }
        }
    }

    // row-sum reduce across the 4 lt lanes, normalize, write out
    #pragma unroll
    for (int i = 0; i < 4; i++) {
        lr[i] += __shfl_xor_sync(0xffffffffu, lr[i], 1);
        lr[i] += __shfl_xor_sync(0xffffffffu, lr[i], 2);
    }
    const float inv0 = 1.0f / lr[0];
    const float inv1 = 1.0f / lr[1];
    const float inv2 = 1.0f / lr[2];
    const float inv3 = 1.0f / lr[3];

    #pragma unroll
    for (int nt = 0; nt < 8; nt++) {
        const int col = h * HD + 8 * nt + 2 * lt;
        float2 r;
        r.x = o[nt][0] * inv0; r.y = o[nt][1] * inv0;
        *(float2*)&out[((size_t)b * Sq + qr     ) * Emb + col] = r;
        r.x = o[nt][2] * inv1; r.y = o[nt][3] * inv1;
        *(float2*)&out[((size_t)b * Sq + qr +  8) * Emb + col] = r;
        r.x = o[nt][4] * inv2; r.y = o[nt][5] * inv2;
        *(float2*)&out[((size_t)b * Sq + qr + 16) * Emb + col] = r;
        r.x = o[nt][6] * inv3; r.y = o[nt][7] * inv3;
        *(float2*)&out[((size_t)b * Sq + qr + 24) * Emb + col] = r;
    }
}

// ---------------------------------------------------------------------------
extern "C" void kernel_launch(void* const* d_in, const int* in_sizes, int n_in,
                              void* d_out, int out_size)
{
    const float* X  = (const float*)d_in[0];
    const float* am = (const float*)d_in[1];
    const float* dm = (const float*)d_in[2];
    const float* Wq = (const float*)d_in[3];
    const float* bq = (const float*)d_in[4];
    const float* Wk = (const float*)d_in[5];
    const float* bk = (const float*)d_in[6];
    const float* Wv = (const float*)d_in[7];
    const float* bv = (const float*)d_in[8];
    float* out = (float*)d_out;

    qkv_kernel<<<dim3(18, 64), 256>>>(X, Wq, bq, Wk, bk, Wv, bv);

    cudaFuncSetAttribute(attn_kernel,
                         cudaFuncAttributeMaxDynamicSharedMemorySize,
                         ATTN_SMEM);
    attn_kernel<<<dim3(Sq / 128, NH, Bsz), 128, ATTN_SMEM>>>(am, dm, out);
}